// round 5
// baseline (speedup 1.0000x reference)
#include <cuda_runtime.h>

#define NN   100000
#define NE   1600000
#define FIN  128
#define HID  64
#define NCLS 40

// ---- scratch (device globals; ONLY referenced inside device code) ----
__device__ float g_h  [NN * HID];   // GEMM output (width <= 64)
__device__ float g_out[NN * HID];   // aggregated output (width <= 64)
__device__ float g_dinv[NN];
__device__ int   g_deg [NN];
__device__ int   g_src [NE];
__device__ int   g_dst [NE];
__device__ float g_norm[NE];
__device__ int   g_is64;            // edge-index dtype probe result

// ------------------------------------------------------------------
// dtype probe: if edge buffer is int64 (values < 2^31), all odd 32-bit
// words are 0. Sample 50K odd words; all-zero => int64, else int32.
// Single block => deterministic, cheap.
// ------------------------------------------------------------------
__global__ void k_detect(const unsigned int* __restrict__ w) {
    __shared__ int nz;
    if (threadIdx.x == 0) nz = 0;
    __syncthreads();
    int found = 0;
    // sample odd words with stride 64: indices 1, 129, 257, ... < 2*NE
    for (int i = 1 + threadIdx.x * 128; i < 2 * NE; i += 256 * 128)
        if (w[i] != 0u) found = 1;
    if (found) atomicOr(&nz, 1);
    __syncthreads();
    if (threadIdx.x == 0) g_is64 = (nz == 0) ? 1 : 0;
}

// ------------------------------------------------------------------
// precompute: degree (incl self-loop), dinv, per-edge norm,
// edge narrowing with dtype branch; indices clamped (never traps).
// ------------------------------------------------------------------
__global__ void k_deg_init() {
    int i = blockIdx.x * blockDim.x + threadIdx.x;
    if (i < NN) g_deg[i] = 1;   // self-loop
}

__global__ void k_edges(const void* __restrict__ eiv) {
    int e = blockIdx.x * blockDim.x + threadIdx.x;
    if (e >= NE) return;
    long long s64, d64;
    if (g_is64) {
        const long long* ei = (const long long*)eiv;
        s64 = ei[e];
        d64 = ei[NE + e];
    } else {
        const int* ei = (const int*)eiv;
        s64 = ei[e];
        d64 = ei[NE + e];
    }
    int s = (s64 < 0) ? 0 : (s64 >= NN ? NN - 1 : (int)s64);
    int d = (d64 < 0) ? 0 : (d64 >= NN ? NN - 1 : (int)d64);
    g_src[e] = s;
    g_dst[e] = d;
    atomicAdd(&g_deg[d], 1);
}

__global__ void k_dinv() {
    int i = blockIdx.x * blockDim.x + threadIdx.x;
    if (i < NN) g_dinv[i] = rsqrtf((float)g_deg[i]);
}

__global__ void k_norm() {
    int e = blockIdx.x * blockDim.x + threadIdx.x;
    if (e >= NE) return;
    g_norm[e] = g_dinv[g_src[e]] * g_dinv[g_dst[e]];
}

// ------------------------------------------------------------------
// GEMM: g_h[n,F] = act(Xsrc[n,K]) @ W[K,F]
// Xsrc = external X (layer 1) or g_out (layers 2,3; FROMG).
// act = identity or relu(x + bias_prev) fused (HASB).
// W resident in smem; RM x RF register tile per thread. 256 thr/blk.
// ------------------------------------------------------------------
template <int K, int F, int RF, int RM, bool HASB, bool FROMG>
__global__ void k_gemm(const float* __restrict__ X,
                       const float* __restrict__ W,
                       const float* __restrict__ bin) {
    constexpr int NF = F / RF;        // threads along F
    constexpr int MT = 256 / NF;      // threads along M
    constexpr int TM = MT * RM;       // rows per block

    const float* __restrict__ Xp = FROMG ? (const float*)g_out : X;

    __shared__ float Ws[K * F];
    __shared__ float Bs[K];

    int tid = threadIdx.x;
    for (int i = tid; i < K * F; i += 256) Ws[i] = W[i];
    if (HASB) {
        for (int i = tid; i < K; i += 256) Bs[i] = bin[i];
    }
    __syncthreads();

    int fth  = tid % NF;
    int mth  = tid / NF;
    int f0   = fth * RF;
    int row0 = blockIdx.x * TM + mth * RM;

    float acc[RM][RF];
#pragma unroll
    for (int m = 0; m < RM; m++)
#pragma unroll
        for (int j = 0; j < RF; j++) acc[m][j] = 0.f;

#pragma unroll 8
    for (int k = 0; k < K; k++) {
        float xv[RM];
#pragma unroll
        for (int m = 0; m < RM; m++) {
            int r = row0 + m;
            float v = (r < NN) ? Xp[r * K + k] : 0.f;
            if (HASB) v = fmaxf(v + Bs[k], 0.f);
            xv[m] = v;
        }
#pragma unroll
        for (int j = 0; j < RF; j++) {
            float wv = Ws[k * F + f0 + j];
#pragma unroll
            for (int m = 0; m < RM; m++)
                acc[m][j] = fmaf(xv[m], wv, acc[m][j]);
        }
    }

#pragma unroll
    for (int m = 0; m < RM; m++) {
        int r = row0 + m;
        if (r < NN) {
#pragma unroll
            for (int j = 0; j < RF; j++)
                g_h[r * F + f0 + j] = acc[m][j];
        }
    }
}

// ------------------------------------------------------------------
// aggregation: g_out[i] = dinv^2 * g_h[i]  (self-loop; doubles as init)
// then scatter: g_out[dst] += g_h[src] * norm[e]  (atomic, result unused)
// ------------------------------------------------------------------
template <int F>
__global__ void k_selfinit() {
    int i = blockIdx.x * blockDim.x + threadIdx.x;
    if (i >= NN * F) return;
    int node = i / F;
    float di = g_dinv[node];
    g_out[i] = g_h[i] * di * di;
}

template <int F>
__global__ void k_scatter() {
    int i = blockIdx.x * blockDim.x + threadIdx.x;
    if (i >= NE * F) return;
    int e = i / F;
    int f = i - e * F;
    float v = g_h[g_src[e] * F + f] * g_norm[e];
    atomicAdd(&g_out[g_dst[e] * F + f], v);
}

// ------------------------------------------------------------------
// epilogue: relu(g_out + b3) then log_softmax over 40 classes.
// one warp per node; lanes 0..31 hold f, lanes 0..7 also hold f+32.
// ------------------------------------------------------------------
__global__ void k_lsm(const float* __restrict__ b3, float* __restrict__ out) {
    int gw   = (blockIdx.x * blockDim.x + threadIdx.x) >> 5;
    int lane = threadIdx.x & 31;
    if (gw >= NN) return;

    const float* p = g_out + gw * NCLS;
    float v0 = fmaxf(p[lane] + b3[lane], 0.f);
    float v1 = (lane < 8) ? fmaxf(p[32 + lane] + b3[32 + lane], 0.f) : -1e30f;

    float m = fmaxf(v0, v1);
#pragma unroll
    for (int o = 16; o > 0; o >>= 1)
        m = fmaxf(m, __shfl_xor_sync(0xFFFFFFFFu, m, o));

    float s = __expf(v0 - m) + ((lane < 8) ? __expf(v1 - m) : 0.f);
#pragma unroll
    for (int o = 16; o > 0; o >>= 1)
        s += __shfl_xor_sync(0xFFFFFFFFu, s, o);

    float lse = m + __logf(s);
    out[gw * NCLS + lane] = v0 - lse;
    if (lane < 8) out[gw * NCLS + 32 + lane] = v1 - lse;
}

extern "C" void kernel_launch(void* const* d_in, const int* in_sizes, int n_in,
                              void* d_out, int out_size) {
    // ---- bind inputs BY ELEMENT COUNT (robust to metadata ordering) ----
    const float* x  = 0;
    const void*  ei = 0;
    const float *W1 = 0, *W2 = 0, *W3 = 0, *b1 = 0, *b2 = 0, *b3 = 0;
    for (int i = 0; i < n_in; i++) {
        long long sz = in_sizes[i];
        const void* p = d_in[i];
        if      (sz == (long long)NN * FIN)  x  = (const float*)p;      // 12.8M
        else if (sz == 2LL * NE)             ei = p;                    // 3.2M
        else if (sz == FIN * HID)            W1 = (const float*)p;      // 8192
        else if (sz == HID * HID)            W2 = (const float*)p;      // 4096
        else if (sz == HID * NCLS)           W3 = (const float*)p;      // 2560
        else if (sz == NCLS)                 b3 = (const float*)p;      // 40
        else if (sz == HID) {                                           // 64, 64
            if (!b1) b1 = (const float*)p; else b2 = (const float*)p;
        }
    }
    float* out = (float*)d_out;
    if (!x || !ei || !W1 || !W2 || !W3 || !b1 || !b2 || !b3) return;

    const int TB = 256;
    int gN = (NN + TB - 1) / TB;
    int gE = (NE + TB - 1) / TB;

    // --- edge dtype probe + degree / norm precompute ---
    k_detect<<<1, TB>>>((const unsigned int*)ei);
    k_deg_init<<<gN, TB>>>();
    k_edges<<<gE, TB>>>(ei);
    k_dinv<<<gN, TB>>>();
    k_norm<<<gE, TB>>>();

    // --- layer 1: 128 -> 64 ---
    {
        constexpr int TM = (256 / (64 / 4)) * 4;   // 64 rows/block
        k_gemm<FIN, HID, 4, 4, false, false><<<(NN + TM - 1) / TM, TB>>>(x, W1, b3);
        k_selfinit<HID><<<(NN * HID + TB - 1) / TB, TB>>>();
        k_scatter<HID><<<(NE * HID + TB - 1) / TB, TB>>>();
    }
    // --- layer 2: 64 -> 64 (relu(prev + b1) fused into GEMM input) ---
    {
        constexpr int TM = (256 / (64 / 4)) * 4;
        k_gemm<HID, HID, 4, 4, true, true><<<(NN + TM - 1) / TM, TB>>>(x, W2, b1);
        k_selfinit<HID><<<(NN * HID + TB - 1) / TB, TB>>>();
        k_scatter<HID><<<(NE * HID + TB - 1) / TB, TB>>>();
    }
    // --- layer 3: 64 -> 40 (relu(prev + b2) fused into GEMM input) ---
    {
        constexpr int TM = (256 / (40 / 5)) * 4;   // 128 rows/block
        k_gemm<HID, NCLS, 5, 4, true, true><<<(NN + TM - 1) / TM, TB>>>(x, W3, b2);
        k_selfinit<NCLS><<<(NN * NCLS + TB - 1) / TB, TB>>>();
        k_scatter<NCLS><<<(NE * NCLS + TB - 1) / TB, TB>>>();
    }

    // --- epilogue: bias + relu + log_softmax ---
    k_lsm<<<(NN + 7) / 8, TB>>>(b3, out);
}

// round 7
// speedup vs baseline: 1.8753x; 1.8753x over previous
#include <cuda_runtime.h>

#define NN   100000
#define NE   1600000
#define FIN  128
#define HID  64
#define NCLS 40

// ---- scratch (device globals; ONLY referenced inside device code) ----
__device__ float g_h   [NN * HID];    // GEMM output (width <= 64)
__device__ float g_out [NN * HID];    // aggregated output (width 64)
__device__ float g_dinv[NN];
__device__ int   g_cnt [NN];          // in-degree (excl self-loop)
__device__ int   g_cur [NN];          // fill cursors
__device__ int   g_off [NN + 1];      // CSR offsets
__device__ int2  g_csr [NE];          // packed {src, norm-bits} sorted by dst
__device__ int   g_is64;              // edge-index dtype probe

// ------------------------------------------------------------------
// dtype probe: int64 edge values < 2^31 => all odd 32-bit words zero.
// ------------------------------------------------------------------
__global__ void k_detect(const unsigned int* __restrict__ w) {
    __shared__ int nz;
    if (threadIdx.x == 0) nz = 0;
    __syncthreads();
    int found = 0;
    for (int i = 1 + threadIdx.x * 128; i < 2 * NE; i += 256 * 128)
        if (w[i] != 0u) found = 1;
    if (found) atomicOr(&nz, 1);
    __syncthreads();
    if (threadIdx.x == 0) g_is64 = (nz == 0) ? 1 : 0;
}

__device__ __forceinline__ int edge_at(const void* eiv, int idx) {
    long long v = g_is64 ? ((const long long*)eiv)[idx] : (long long)((const int*)eiv)[idx];
    return (v < 0) ? 0 : (v >= NN ? NN - 1 : (int)v);
}

// ------------------------------------------------------------------
// CSR build: zero -> histogram -> dinv -> scan -> fill
// ------------------------------------------------------------------
__global__ void k_zero() {
    int i = blockIdx.x * blockDim.x + threadIdx.x;
    if (i < NN) { g_cnt[i] = 0; g_cur[i] = 0; }
}

__global__ void k_hist(const void* __restrict__ eiv) {
    int e = blockIdx.x * blockDim.x + threadIdx.x;
    if (e >= NE) return;
    atomicAdd(&g_cnt[edge_at(eiv, NE + e)], 1);
}

__global__ void k_dinv() {
    int i = blockIdx.x * blockDim.x + threadIdx.x;
    if (i < NN) g_dinv[i] = rsqrtf((float)(g_cnt[i] + 1));   // +1 self-loop
}

#define SCAN_T 1024
__global__ void k_scan() {
    int t = threadIdx.x;
    const int chunk = (NN + SCAN_T - 1) / SCAN_T;
    int start = t * chunk;
    int end = start + chunk; if (end > NN) end = NN;
    int s = 0;
    for (int i = start; i < end; i++) { int c = g_cnt[i]; g_off[i] = s; s += c; }
    __shared__ int sums[SCAN_T];
    sums[t] = s;
    __syncthreads();
    for (int o = 1; o < SCAN_T; o <<= 1) {
        int v = (t >= o) ? sums[t - o] : 0;
        __syncthreads();
        sums[t] += v;
        __syncthreads();
    }
    int base = (t == 0) ? 0 : sums[t - 1];
    for (int i = start; i < end; i++) g_off[i] += base;
    if (t == SCAN_T - 1) g_off[NN] = sums[SCAN_T - 1];
}

__global__ void k_fill(const void* __restrict__ eiv) {
    int e = blockIdx.x * blockDim.x + threadIdx.x;
    if (e >= NE) return;
    int s = edge_at(eiv, e);
    int d = edge_at(eiv, NE + e);
    float nrm = g_dinv[s] * g_dinv[d];
    int idx = g_off[d] + atomicAdd(&g_cur[d], 1);
    g_csr[idx] = make_int2(s, __float_as_int(nrm));
}

// ------------------------------------------------------------------
// GEMM: g_h[n,F] = act(Xsrc[n,K]) @ W[K,F]
// ------------------------------------------------------------------
template <int K, int F, int RF, int RM, bool HASB, bool FROMG>
__global__ void k_gemm(const float* __restrict__ X,
                       const float* __restrict__ W,
                       const float* __restrict__ bin) {
    constexpr int NF = F / RF;
    constexpr int MT = 256 / NF;
    constexpr int TM = MT * RM;

    const float* __restrict__ Xp = FROMG ? (const float*)g_out : X;

    __shared__ float Ws[K * F];
    __shared__ float Bs[K];

    int tid = threadIdx.x;
    for (int i = tid; i < K * F; i += 256) Ws[i] = W[i];
    if (HASB) for (int i = tid; i < K; i += 256) Bs[i] = bin[i];
    __syncthreads();

    int fth  = tid % NF;
    int mth  = tid / NF;
    int f0   = fth * RF;
    int row0 = blockIdx.x * TM + mth * RM;

    float acc[RM][RF];
#pragma unroll
    for (int m = 0; m < RM; m++)
#pragma unroll
        for (int j = 0; j < RF; j++) acc[m][j] = 0.f;

#pragma unroll 8
    for (int k = 0; k < K; k++) {
        float xv[RM];
#pragma unroll
        for (int m = 0; m < RM; m++) {
            int r = row0 + m;
            float v = (r < NN) ? Xp[r * K + k] : 0.f;
            if (HASB) v = fmaxf(v + Bs[k], 0.f);
            xv[m] = v;
        }
#pragma unroll
        for (int j = 0; j < RF; j++) {
            float wv = Ws[k * F + f0 + j];
#pragma unroll
            for (int m = 0; m < RM; m++)
                acc[m][j] = fmaf(xv[m], wv, acc[m][j]);
        }
    }

#pragma unroll
    for (int m = 0; m < RM; m++) {
        int r = row0 + m;
        if (r < NN) {
#pragma unroll
            for (int j = 0; j < RF; j++)
                g_h[r * F + f0 + j] = acc[m][j];
        }
    }
}

// ------------------------------------------------------------------
// CSR gather aggregation, F=64: one warp per dst node, no atomics.
// acc init = self-loop term. Writes g_out.
// ------------------------------------------------------------------
__global__ void k_agg64() {
    int gw   = (blockIdx.x * blockDim.x + threadIdx.x) >> 5;
    int lane = threadIdx.x & 31;
    if (gw >= NN) return;

    float di = g_dinv[gw];
    float sl = di * di;
    float a0 = g_h[gw * 64 + lane]      * sl;
    float a1 = g_h[gw * 64 + 32 + lane] * sl;

    int b = g_off[gw], e = g_off[gw + 1];
#pragma unroll 4
    for (int i = b; i < e; i++) {
        int2 ed = g_csr[i];                       // 8B broadcast
        float w = __int_as_float(ed.y);
        const float* hp = g_h + ed.x * 64;
        a0 = fmaf(hp[lane],      w, a0);
        a1 = fmaf(hp[32 + lane], w, a1);
    }
    g_out[gw * 64 + lane]      = a0;
    g_out[gw * 64 + 32 + lane] = a1;
}

// ------------------------------------------------------------------
// Layer-3 aggregation (F=40) fused with bias+relu+log_softmax.
// Writes final output directly.
// ------------------------------------------------------------------
__global__ void k_agg40_lsm(const float* __restrict__ b3, float* __restrict__ out) {
    int gw   = (blockIdx.x * blockDim.x + threadIdx.x) >> 5;
    int lane = threadIdx.x & 31;
    if (gw >= NN) return;

    float di = g_dinv[gw];
    float sl = di * di;
    float a0 = g_h[gw * NCLS + lane] * sl;
    float a1 = (lane < 8) ? g_h[gw * NCLS + 32 + lane] * sl : 0.f;

    int b = g_off[gw], e = g_off[gw + 1];
#pragma unroll 4
    for (int i = b; i < e; i++) {
        int2 ed = g_csr[i];
        float w = __int_as_float(ed.y);
        const float* hp = g_h + ed.x * NCLS;
        a0 = fmaf(hp[lane], w, a0);
        float v1 = (lane < 8) ? hp[32 + lane] : 0.f;
        a1 = fmaf(v1, w, a1);
    }

    // bias + relu
    float v0 = fmaxf(a0 + b3[lane], 0.f);
    float v1 = (lane < 8) ? fmaxf(a1 + b3[32 + lane], 0.f) : -1e30f;

    // log_softmax over 40 values held across the warp
    float m = fmaxf(v0, v1);
#pragma unroll
    for (int o = 16; o > 0; o >>= 1)
        m = fmaxf(m, __shfl_xor_sync(0xFFFFFFFFu, m, o));

    float s = __expf(v0 - m) + ((lane < 8) ? __expf(v1 - m) : 0.f);
#pragma unroll
    for (int o = 16; o > 0; o >>= 1)
        s += __shfl_xor_sync(0xFFFFFFFFu, s, o);

    float lse = m + __logf(s);
    out[gw * NCLS + lane] = v0 - lse;
    if (lane < 8) out[gw * NCLS + 32 + lane] = v1 - lse;
}

extern "C" void kernel_launch(void* const* d_in, const int* in_sizes, int n_in,
                              void* d_out, int out_size) {
    // ---- bind inputs BY ELEMENT COUNT (robust to metadata ordering) ----
    const float* x  = 0;
    const void*  ei = 0;
    const float *W1 = 0, *W2 = 0, *W3 = 0, *b1 = 0, *b2 = 0, *b3 = 0;
    for (int i = 0; i < n_in; i++) {
        long long sz = in_sizes[i];
        const void* p = d_in[i];
        if      (sz == (long long)NN * FIN)  x  = (const float*)p;
        else if (sz == 2LL * NE)             ei = p;
        else if (sz == FIN * HID)            W1 = (const float*)p;
        else if (sz == HID * HID)            W2 = (const float*)p;
        else if (sz == HID * NCLS)           W3 = (const float*)p;
        else if (sz == NCLS)                 b3 = (const float*)p;
        else if (sz == HID) {
            if (!b1) b1 = (const float*)p; else b2 = (const float*)p;
        }
    }
    float* out = (float*)d_out;
    if (!x || !ei || !W1 || !W2 || !W3 || !b1 || !b2 || !b3) return;

    const int TB = 256;
    int gN = (NN + TB - 1) / TB;
    int gE = (NE + TB - 1) / TB;
    int gW = (NN * 32 + TB - 1) / TB;   // warp-per-node grids

    // --- CSR build ---
    k_detect<<<1, TB>>>((const unsigned int*)ei);
    k_zero<<<gN, TB>>>();
    k_hist<<<gE, TB>>>(ei);
    k_dinv<<<gN, TB>>>();
    k_scan<<<1, SCAN_T>>>();
    k_fill<<<gE, TB>>>(ei);

    // --- layer 1: 128 -> 64 ---
    {
        constexpr int TM = (256 / (64 / 4)) * 4;   // 64 rows/block
        k_gemm<FIN, HID, 4, 4, false, false><<<(NN + TM - 1) / TM, TB>>>(x, W1, b3);
        k_agg64<<<gW, TB>>>();
    }
    // --- layer 2: 64 -> 64 (relu(prev + b1) fused into GEMM input) ---
    {
        constexpr int TM = (256 / (64 / 4)) * 4;
        k_gemm<HID, HID, 4, 4, true, true><<<(NN + TM - 1) / TM, TB>>>(x, W2, b1);
        k_agg64<<<gW, TB>>>();
    }
    // --- layer 3: 64 -> 40 + fused bias/relu/log_softmax ---
    {
        constexpr int TM = (256 / (40 / 5)) * 4;   // 128 rows/block
        k_gemm<HID, NCLS, 5, 4, true, true><<<(NN + TM - 1) / TM, TB>>>(x, W3, b2);
        k_agg40_lsm<<<gW, TB>>>(b3, out);
    }
}

// round 8
// speedup vs baseline: 2.0276x; 1.0812x over previous
#include <cuda_runtime.h>

#define NN   100000
#define NE   1600000
#define FIN  128
#define HID  64
#define NCLS 40

// ---- scratch (device globals; ONLY referenced inside device code) ----
__device__ __align__(16) float g_h   [NN * HID];   // GEMM output (width <= 64)
__device__ __align__(16) float g_out [NN * HID];   // aggregated output (width 64)
__device__ float g_dinv[NN];
__device__ int   g_cnt [NN];          // in-degree (excl self-loop)
__device__ int   g_cur [NN];          // fill cursors
__device__ int   g_off [NN + 1];      // CSR offsets
__device__ int2  g_csr [NE];          // packed {src, norm-bits} sorted by dst
__device__ int   g_is64;              // edge-index dtype probe

// ------------------------------------------------------------------
// dtype probe: int64 edge values < 2^31 => all odd 32-bit words zero.
// ------------------------------------------------------------------
__global__ void k_detect(const unsigned int* __restrict__ w) {
    __shared__ int nz;
    if (threadIdx.x == 0) nz = 0;
    __syncthreads();
    int found = 0;
    for (int i = 1 + threadIdx.x * 128; i < 2 * NE; i += 256 * 128)
        if (w[i] != 0u) found = 1;
    if (found) atomicOr(&nz, 1);
    __syncthreads();
    if (threadIdx.x == 0) g_is64 = (nz == 0) ? 1 : 0;
}

__device__ __forceinline__ int edge_at(const void* eiv, int idx) {
    long long v = g_is64 ? ((const long long*)eiv)[idx] : (long long)((const int*)eiv)[idx];
    return (v < 0) ? 0 : (v >= NN ? NN - 1 : (int)v);
}

// ------------------------------------------------------------------
// CSR build: zero -> histogram -> dinv -> scan -> fill
// ------------------------------------------------------------------
__global__ void k_zero() {
    int i = blockIdx.x * blockDim.x + threadIdx.x;
    if (i < NN) { g_cnt[i] = 0; g_cur[i] = 0; }
}

__global__ void k_hist(const void* __restrict__ eiv) {
    int e = blockIdx.x * blockDim.x + threadIdx.x;
    if (e >= NE) return;
    atomicAdd(&g_cnt[edge_at(eiv, NE + e)], 1);
}

__global__ void k_dinv() {
    int i = blockIdx.x * blockDim.x + threadIdx.x;
    if (i < NN) g_dinv[i] = rsqrtf((float)(g_cnt[i] + 1));   // +1 self-loop
}

#define SCAN_T 1024
__global__ void k_scan() {
    int t = threadIdx.x;
    const int chunk = (NN + SCAN_T - 1) / SCAN_T;
    int start = t * chunk;
    int end = start + chunk; if (end > NN) end = NN;
    int s = 0;
    for (int i = start; i < end; i++) { int c = g_cnt[i]; g_off[i] = s; s += c; }
    __shared__ int sums[SCAN_T];
    sums[t] = s;
    __syncthreads();
    for (int o = 1; o < SCAN_T; o <<= 1) {
        int v = (t >= o) ? sums[t - o] : 0;
        __syncthreads();
        sums[t] += v;
        __syncthreads();
    }
    int base = (t == 0) ? 0 : sums[t - 1];
    for (int i = start; i < end; i++) g_off[i] += base;
    if (t == SCAN_T - 1) g_off[NN] = sums[SCAN_T - 1];
}

__global__ void k_fill(const void* __restrict__ eiv) {
    int e = blockIdx.x * blockDim.x + threadIdx.x;
    if (e >= NE) return;
    int s = edge_at(eiv, e);
    int d = edge_at(eiv, NE + e);
    float nrm = g_dinv[s] * g_dinv[d];
    int idx = g_off[d] + atomicAdd(&g_cur[d], 1);
    g_csr[idx] = make_int2(s, __float_as_int(nrm));
}

// ------------------------------------------------------------------
// GEMM: g_h[n,F] = act(Xsrc[n,K]) @ W[K,F]   (float4 X loads)
// ------------------------------------------------------------------
template <int K, int F, int RF, int RM, bool HASB, bool FROMG>
__global__ void k_gemm(const float* __restrict__ X,
                       const float* __restrict__ W,
                       const float* __restrict__ bin) {
    constexpr int NF = F / RF;
    constexpr int MT = 256 / NF;
    constexpr int TM = MT * RM;

    const float4* __restrict__ X4 =
        FROMG ? (const float4*)g_out : (const float4*)X;

    __shared__ float Ws[K * F];
    __shared__ float Bs[K];

    int tid = threadIdx.x;
    for (int i = tid; i < K * F; i += 256) Ws[i] = W[i];
    if (HASB) for (int i = tid; i < K; i += 256) Bs[i] = bin[i];
    __syncthreads();

    int fth  = tid % NF;
    int mth  = tid / NF;
    int f0   = fth * RF;
    int row0 = blockIdx.x * TM + mth * RM;

    float acc[RM][RF];
#pragma unroll
    for (int m = 0; m < RM; m++)
#pragma unroll
        for (int j = 0; j < RF; j++) acc[m][j] = 0.f;

#pragma unroll
    for (int k4 = 0; k4 < K; k4 += 4) {
        float xr[RM][4];
#pragma unroll
        for (int m = 0; m < RM; m++) {
            int r = row0 + m;
            float4 v = (r < NN) ? X4[(r * K + k4) >> 2]
                                : make_float4(0.f, 0.f, 0.f, 0.f);
            if (HASB) {
                v.x = fmaxf(v.x + Bs[k4 + 0], 0.f);
                v.y = fmaxf(v.y + Bs[k4 + 1], 0.f);
                v.z = fmaxf(v.z + Bs[k4 + 2], 0.f);
                v.w = fmaxf(v.w + Bs[k4 + 3], 0.f);
            }
            xr[m][0] = v.x; xr[m][1] = v.y; xr[m][2] = v.z; xr[m][3] = v.w;
        }
#pragma unroll
        for (int kk = 0; kk < 4; kk++) {
#pragma unroll
            for (int j = 0; j < RF; j++) {
                float wv = Ws[(k4 + kk) * F + f0 + j];
#pragma unroll
                for (int m = 0; m < RM; m++)
                    acc[m][j] = fmaf(xr[m][kk], wv, acc[m][j]);
            }
        }
    }

#pragma unroll
    for (int m = 0; m < RM; m++) {
        int r = row0 + m;
        if (r < NN) {
#pragma unroll
            for (int j = 0; j < RF; j++)
                g_h[r * F + f0 + j] = acc[m][j];
        }
    }
}

// ------------------------------------------------------------------
// CSR gather aggregation, F=64: warp per dst node, float2 lanes,
// 4-edge batches for MLP. acc init = self-loop term.
// ------------------------------------------------------------------
__global__ void k_agg64() {
    int gw   = (blockIdx.x * blockDim.x + threadIdx.x) >> 5;
    int lane = threadIdx.x & 31;
    if (gw >= NN) return;

    const float2* __restrict__ h2 = (const float2*)g_h;   // row = 32 float2

    float di = g_dinv[gw];
    float sl = di * di;
    float2 a = h2[gw * 32 + lane];
    a.x *= sl; a.y *= sl;

    int b = g_off[gw], e = g_off[gw + 1];
    int i = b;
    for (; i + 4 <= e; i += 4) {
        int2 e0 = g_csr[i];
        int2 e1 = g_csr[i + 1];
        int2 e2 = g_csr[i + 2];
        int2 e3 = g_csr[i + 3];
        float2 h0 = h2[e0.x * 32 + lane];
        float2 h1 = h2[e1.x * 32 + lane];
        float2 hv2 = h2[e2.x * 32 + lane];
        float2 h3 = h2[e3.x * 32 + lane];
        float w0 = __int_as_float(e0.y), w1 = __int_as_float(e1.y);
        float w2 = __int_as_float(e2.y), w3 = __int_as_float(e3.y);
        a.x = fmaf(h0.x, w0, a.x);  a.y = fmaf(h0.y, w0, a.y);
        a.x = fmaf(h1.x, w1, a.x);  a.y = fmaf(h1.y, w1, a.y);
        a.x = fmaf(hv2.x, w2, a.x); a.y = fmaf(hv2.y, w2, a.y);
        a.x = fmaf(h3.x, w3, a.x);  a.y = fmaf(h3.y, w3, a.y);
    }
    for (; i < e; i++) {
        int2 ed = g_csr[i];
        float w = __int_as_float(ed.y);
        float2 hv = h2[ed.x * 32 + lane];
        a.x = fmaf(hv.x, w, a.x);
        a.y = fmaf(hv.y, w, a.y);
    }
    ((float2*)g_out)[gw * 32 + lane] = a;
}

// ------------------------------------------------------------------
// Layer-3 aggregation (F=40, 20 float2 lanes) fused with
// bias+relu+log_softmax. Writes final output directly.
// ------------------------------------------------------------------
__global__ void k_agg40_lsm(const float* __restrict__ b3, float* __restrict__ out) {
    int gw   = (blockIdx.x * blockDim.x + threadIdx.x) >> 5;
    int lane = threadIdx.x & 31;
    if (gw >= NN) return;

    const float2* __restrict__ h2 = (const float2*)g_h;   // row = 20 float2
    bool act = lane < 20;

    float di = g_dinv[gw];
    float sl = di * di;
    float2 a = act ? h2[gw * 20 + lane] : make_float2(0.f, 0.f);
    a.x *= sl; a.y *= sl;

    int b = g_off[gw], e = g_off[gw + 1];
    int i = b;
    for (; i + 4 <= e; i += 4) {
        int2 e0 = g_csr[i];
        int2 e1 = g_csr[i + 1];
        int2 e2 = g_csr[i + 2];
        int2 e3 = g_csr[i + 3];
        float2 z = make_float2(0.f, 0.f);
        float2 h0 = act ? h2[e0.x * 20 + lane] : z;
        float2 h1 = act ? h2[e1.x * 20 + lane] : z;
        float2 hv2 = act ? h2[e2.x * 20 + lane] : z;
        float2 h3 = act ? h2[e3.x * 20 + lane] : z;
        float w0 = __int_as_float(e0.y), w1 = __int_as_float(e1.y);
        float w2 = __int_as_float(e2.y), w3 = __int_as_float(e3.y);
        a.x = fmaf(h0.x, w0, a.x);  a.y = fmaf(h0.y, w0, a.y);
        a.x = fmaf(h1.x, w1, a.x);  a.y = fmaf(h1.y, w1, a.y);
        a.x = fmaf(hv2.x, w2, a.x); a.y = fmaf(hv2.y, w2, a.y);
        a.x = fmaf(h3.x, w3, a.x);  a.y = fmaf(h3.y, w3, a.y);
    }
    for (; i < e; i++) {
        int2 ed = g_csr[i];
        float w = __int_as_float(ed.y);
        float2 hv = act ? h2[ed.x * 20 + lane] : make_float2(0.f, 0.f);
        a.x = fmaf(hv.x, w, a.x);
        a.y = fmaf(hv.y, w, a.y);
    }

    // bias + relu (two classes per active lane)
    float v0 = -1e30f, v1 = -1e30f;
    if (act) {
        const float2* b2 = (const float2*)b3;
        float2 bb = b2[lane];
        v0 = fmaxf(a.x + bb.x, 0.f);
        v1 = fmaxf(a.y + bb.y, 0.f);
    }

    // log_softmax over 40 values spread across 20 lanes x 2
    float m = fmaxf(v0, v1);
#pragma unroll
    for (int o = 16; o > 0; o >>= 1)
        m = fmaxf(m, __shfl_xor_sync(0xFFFFFFFFu, m, o));

    float s = act ? (__expf(v0 - m) + __expf(v1 - m)) : 0.f;
#pragma unroll
    for (int o = 16; o > 0; o >>= 1)
        s += __shfl_xor_sync(0xFFFFFFFFu, s, o);

    float lse = m + __logf(s);
    if (act) {
        float2 r = make_float2(v0 - lse, v1 - lse);
        ((float2*)out)[gw * 20 + lane] = r;
    }
}

extern "C" void kernel_launch(void* const* d_in, const int* in_sizes, int n_in,
                              void* d_out, int out_size) {
    // ---- bind inputs BY ELEMENT COUNT (robust to metadata ordering) ----
    const float* x  = 0;
    const void*  ei = 0;
    const float *W1 = 0, *W2 = 0, *W3 = 0, *b1 = 0, *b2 = 0, *b3 = 0;
    for (int i = 0; i < n_in; i++) {
        long long sz = in_sizes[i];
        const void* p = d_in[i];
        if      (sz == (long long)NN * FIN)  x  = (const float*)p;
        else if (sz == 2LL * NE)             ei = p;
        else if (sz == FIN * HID)            W1 = (const float*)p;
        else if (sz == HID * HID)            W2 = (const float*)p;
        else if (sz == HID * NCLS)           W3 = (const float*)p;
        else if (sz == NCLS)                 b3 = (const float*)p;
        else if (sz == HID) {
            if (!b1) b1 = (const float*)p; else b2 = (const float*)p;
        }
    }
    float* out = (float*)d_out;
    if (!x || !ei || !W1 || !W2 || !W3 || !b1 || !b2 || !b3) return;

    const int TB = 256;
    int gN = (NN + TB - 1) / TB;
    int gE = (NE + TB - 1) / TB;
    int gW = (NN * 32 + TB - 1) / TB;   // warp-per-node grids

    // --- CSR build ---
    k_detect<<<1, TB>>>((const unsigned int*)ei);
    k_zero<<<gN, TB>>>();
    k_hist<<<gE, TB>>>(ei);
    k_dinv<<<gN, TB>>>();
    k_scan<<<1, SCAN_T>>>();
    k_fill<<<gE, TB>>>(ei);

    // --- layer 1: 128 -> 64 ---
    {
        constexpr int TM = (256 / (64 / 4)) * 4;   // 64 rows/block
        k_gemm<FIN, HID, 4, 4, false, false><<<(NN + TM - 1) / TM, TB>>>(x, W1, b3);
        k_agg64<<<gW, TB>>>();
    }
    // --- layer 2: 64 -> 64 (relu(prev + b1) fused into GEMM input) ---
    {
        constexpr int TM = (256 / (64 / 4)) * 4;
        k_gemm<HID, HID, 4, 4, true, true><<<(NN + TM - 1) / TM, TB>>>(x, W2, b1);
        k_agg64<<<gW, TB>>>();
    }
    // --- layer 3: 64 -> 40 + fused bias/relu/log_softmax ---
    {
        constexpr int TM = (256 / (40 / 5)) * 4;   // 128 rows/block
        k_gemm<HID, NCLS, 5, 4, true, true><<<(NN + TM - 1) / TM, TB>>>(x, W3, b2);
        k_agg40_lsm<<<gW, TB>>>(b3, out);
    }
}